// round 3
// baseline (speedup 1.0000x reference)
#include <cuda_runtime.h>

#define HID 8192
#define BATCH 512
#define NIN 16
#define RANK 8
#define NOUT 4
#define HSPLIT 8   // H-chunks for k_rank / k_out
#define BSPLIT 4   // batch-chunks for k_update

// scratch: partials + final u; last-block-reduces counters (auto-wrap => replay-safe)
__device__ float g_u_part[HSPLIT][BATCH * RANK];
__device__ float g_u[BATCH * RANK];
__device__ float g_out_part[HSPLIT][BATCH * NOUT];
__device__ unsigned int g_cnt1[BATCH / 4];
__device__ unsigned int g_cnt3[BATCH / 4];

typedef unsigned long long ull;

__device__ __forceinline__ void ffma2(ull& d, ull a, ull b) {
    asm("fma.rn.f32x2 %0, %1, %2, %0;" : "+l"(d) : "l"(a), "l"(b));
}
__device__ __forceinline__ void unpack2(float& lo, float& hi, ull v) {
    asm("mov.b64 {%0, %1}, %2;" : "=f"(lo), "=f"(hi) : "l"(v));
}

// ---------------------------------------------------------------------------
// K1: partial u over one H-chunk of 1024; last arriving block per batch-group
// combines the 8 partials deterministically (fixed loop order) into g_u.
// grid = (BATCH/4, HSPLIT) = 1024 blocks, 256 threads.
// ---------------------------------------------------------------------------
__global__ void __launch_bounds__(256, 3) k_rank(const float* __restrict__ h,
                                                 const float* __restrict__ R) {
    const int t = threadIdx.x;
    const int bbase = blockIdx.x * 4;
    const int hs = blockIdx.y;
    const int j = hs * (HID / HSPLIT) + t * 4;

    // tanh of 4 batch rows first (16 regs), then stream R rows with FMA
    float th[4][4];
#pragma unroll
    for (int bl = 0; bl < 4; bl++) {
        float4 h4 = *(const float4*)(h + (bbase + bl) * HID + j);
        th[bl][0] = __tanhf(h4.x);
        th[bl][1] = __tanhf(h4.y);
        th[bl][2] = __tanhf(h4.z);
        th[bl][3] = __tanhf(h4.w);
    }

    float acc[4][8];
#pragma unroll
    for (int r = 0; r < 8; r++) {
        float4 rv = *(const float4*)(R + r * HID + j);
#pragma unroll
        for (int bl = 0; bl < 4; bl++) {
            float a = th[bl][0] * rv.x;
            a = fmaf(th[bl][1], rv.y, a);
            a = fmaf(th[bl][2], rv.z, a);
            a = fmaf(th[bl][3], rv.w, a);
            acc[bl][r] = a;
        }
    }

#pragma unroll
    for (int bl = 0; bl < 4; bl++)
#pragma unroll
        for (int r = 0; r < 8; r++)
#pragma unroll
            for (int off = 16; off > 0; off >>= 1)
                acc[bl][r] += __shfl_xor_sync(0xffffffffu, acc[bl][r], off);

    __shared__ float red[8][32];
    const int lane = t & 31, w = t >> 5;
    if (lane == 0) {
#pragma unroll
        for (int bl = 0; bl < 4; bl++)
#pragma unroll
            for (int r = 0; r < 8; r++)
                red[w][bl * 8 + r] = acc[bl][r];
    }
    __syncthreads();
    if (t < 32) {
        float s = 0.0f;
#pragma unroll
        for (int w2 = 0; w2 < 8; w2++) s += red[w2][t];
        // index: bl = t>>3, r = t&7  ->  (bbase+bl)*RANK + r = bbase*RANK + t
        g_u_part[hs][bbase * RANK + t] = s;
    }

    // last-block combine (deterministic: fixed loop order over hs)
    __threadfence();
    __shared__ unsigned int tick;
    if (t == 0) tick = atomicInc(&g_cnt1[blockIdx.x], HSPLIT - 1);
    __syncthreads();
    if (tick == HSPLIT - 1) {
        __threadfence();
        if (t < 32) {
            float s2 = 0.0f;
#pragma unroll
            for (int p = 0; p < HSPLIT; p++)
                s2 += __ldcg(&g_u_part[p][bbase * RANK + t]);
            g_u[bbase * RANK + t] = s2 * (1.0f / (float)HID);
        }
    }
}

// ---------------------------------------------------------------------------
// K2: new_h = 0.9 h + 0.1 (input.W_in[j] + u.L[j])
// grid = (HID/64, BSPLIT) = 512 blocks. Thread owns 4 j-columns, weights in
// registers as f32x2 pairs; loops over its 128-row batch chunk.
// ---------------------------------------------------------------------------
__global__ void __launch_bounds__(256) k_update(const float* __restrict__ input,
                                                const float* __restrict__ hidden,
                                                const float* __restrict__ Win,
                                                const float* __restrict__ L,
                                                float* __restrict__ nh_out) {
    const int t = threadIdx.x;
    const int jg = t & 15;       // 16 groups of 4 j
    const int bs = t >> 4;       // 0..15
    const int j0 = blockIdx.x * 64 + jg * 4;
    const int b0 = blockIdx.y * (BATCH / BSPLIT);

    ull wj[4][8];   // W_in[j][0..15] as 8 pairs
    ull lj[4][4];   // L[j][0..7]     as 4 pairs
#pragma unroll
    for (int jj = 0; jj < 4; jj++) {
        const ull* wr = (const ull*)(Win + (j0 + jj) * NIN);
#pragma unroll
        for (int i = 0; i < 8; i++) wj[jj][i] = wr[i];
        const ull* lr = (const ull*)(L + (j0 + jj) * RANK);
#pragma unroll
        for (int r = 0; r < 4; r++) lj[jj][r] = lr[r];
    }

    for (int bi = bs; bi < BATCH / BSPLIT; bi += 16) {
        const int b = b0 + bi;
        const ull* ip = (const ull*)(input + b * NIN);
        ull ipr[8];
#pragma unroll
        for (int i = 0; i < 8; i++) ipr[i] = ip[i];
        const ull* up = (const ull*)(g_u + b * RANK);
        ull upr[4];
#pragma unroll
        for (int r = 0; r < 4; r++) upr[r] = up[r];

        float4 h4 = *(const float4*)(hidden + b * HID + j0);

        float res[4];
#pragma unroll
        for (int jj = 0; jj < 4; jj++) {
            ull acc = 0ULL;  // (0.0f, 0.0f)
#pragma unroll
            for (int i = 0; i < 8; i++) ffma2(acc, wj[jj][i], ipr[i]);
#pragma unroll
            for (int r = 0; r < 4; r++) ffma2(acc, lj[jj][r], upr[r]);
            float lo, hi;
            unpack2(lo, hi, acc);
            res[jj] = lo + hi;
        }

        float4 o;
        o.x = fmaf(0.1f, res[0], 0.9f * h4.x);
        o.y = fmaf(0.1f, res[1], 0.9f * h4.y);
        o.z = fmaf(0.1f, res[2], 0.9f * h4.z);
        o.w = fmaf(0.1f, res[3], 0.9f * h4.w);
        *(float4*)(nh_out + b * HID + j0) = o;
    }
}

// ---------------------------------------------------------------------------
// K3: partial out over one H-chunk of 1024; last block per batch-group
// combines 8 partials deterministically and writes final out.
// grid = (BATCH/4, HSPLIT) = 1024 blocks.
// ---------------------------------------------------------------------------
__global__ void __launch_bounds__(256, 4) k_out(const float* __restrict__ nh,
                                                const float* __restrict__ Wout,
                                                float* __restrict__ out) {
    const int t = threadIdx.x;
    const int bbase = blockIdx.x * 4;
    const int hs = blockIdx.y;
    const int j = hs * (HID / HSPLIT) + t * 4;

    float th[4][4];
#pragma unroll
    for (int bl = 0; bl < 4; bl++) {
        float4 x = *(const float4*)(nh + (bbase + bl) * HID + j);
        th[bl][0] = __tanhf(x.x);
        th[bl][1] = __tanhf(x.y);
        th[bl][2] = __tanhf(x.z);
        th[bl][3] = __tanhf(x.w);
    }

    float acc[4][4];
#pragma unroll
    for (int o = 0; o < 4; o++) {
        float4 w4 = *(const float4*)(Wout + o * HID + j);
#pragma unroll
        for (int bl = 0; bl < 4; bl++) {
            float a = th[bl][0] * w4.x;
            a = fmaf(th[bl][1], w4.y, a);
            a = fmaf(th[bl][2], w4.z, a);
            a = fmaf(th[bl][3], w4.w, a);
            acc[bl][o] = a;
        }
    }

#pragma unroll
    for (int bl = 0; bl < 4; bl++)
#pragma unroll
        for (int o = 0; o < 4; o++)
#pragma unroll
            for (int off = 16; off > 0; off >>= 1)
                acc[bl][o] += __shfl_xor_sync(0xffffffffu, acc[bl][o], off);

    __shared__ float red[8][16];
    const int lane = t & 31, w = t >> 5;
    if (lane == 0) {
#pragma unroll
        for (int bl = 0; bl < 4; bl++)
#pragma unroll
            for (int o = 0; o < 4; o++)
                red[w][bl * 4 + o] = acc[bl][o];
    }
    __syncthreads();
    if (t < 16) {
        float s = 0.0f;
#pragma unroll
        for (int w2 = 0; w2 < 8; w2++) s += red[w2][t];
        // index: bl = t>>2, o = t&3  ->  (bbase+bl)*NOUT + o = bbase*NOUT + t
        g_out_part[hs][bbase * NOUT + t] = s;
    }

    __threadfence();
    __shared__ unsigned int tick;
    if (t == 0) tick = atomicInc(&g_cnt3[blockIdx.x], HSPLIT - 1);
    __syncthreads();
    if (tick == HSPLIT - 1) {
        __threadfence();
        if (t < 16) {
            float s2 = 0.0f;
#pragma unroll
            for (int p = 0; p < HSPLIT; p++)
                s2 += __ldcg(&g_out_part[p][bbase * NOUT + t]);
            out[bbase * NOUT + t] = s2 * (1.0f / (float)HID);
        }
    }
}

extern "C" void kernel_launch(void* const* d_in, const int* in_sizes, int n_in,
                              void* d_out, int out_size) {
    const float* input  = (const float*)d_in[0];  // [512,16]
    const float* hidden = (const float*)d_in[1];  // [512,8192]
    const float* Win    = (const float*)d_in[2];  // [8192,16]
    const float* L      = (const float*)d_in[3];  // [8192,8]
    const float* R      = (const float*)d_in[4];  // [8,8192]
    const float* Wout   = (const float*)d_in[5];  // [4,8192]

    float* out = (float*)d_out;                   // [512,4] then [512,8192]
    float* nh  = out + BATCH * NOUT;

    k_rank<<<dim3(BATCH / 4, HSPLIT), 256>>>(hidden, R);
    k_update<<<dim3(HID / 64, BSPLIT), 256>>>(input, hidden, Win, L, nh);
    k_out<<<dim3(BATCH / 4, HSPLIT), 256>>>(nh, Wout, out);
}

// round 4
// speedup vs baseline: 1.4992x; 1.4992x over previous
#include <cuda_runtime.h>

#define HID 8192
#define BATCH 512
#define NIN 16
#define RANK 8
#define NOUT 4
#define K1SPLIT 4   // H-chunks for k_rank
#define BSPLIT 8    // batch-chunks for k_update

// scratch: per-chunk partials of u; folded inside k_update (no fences/atomics)
__device__ float g_u_part[K1SPLIT][BATCH * RANK];

typedef unsigned long long ull;

__device__ __forceinline__ void ffma2(ull& d, ull a, ull b) {
    asm("fma.rn.f32x2 %0, %1, %2, %0;" : "+l"(d) : "l"(a), "l"(b));
}
__device__ __forceinline__ void unpack2(float& lo, float& hi, ull v) {
    asm("mov.b64 {%0, %1}, %2;" : "=f"(lo), "=f"(hi) : "l"(v));
}

// ---------------------------------------------------------------------------
// K1: partial u over one H-chunk of 2048.
// grid = (BATCH/4, K1SPLIT) = 512 blocks, 256 threads, 2 float4-iters/thread.
// Multi-value warp allreduce: 32 accs in 31 SHFLs (lane L ends with acc[L]).
// ---------------------------------------------------------------------------
__global__ void __launch_bounds__(256) k_rank(const float* __restrict__ h,
                                              const float* __restrict__ R) {
    const int t = threadIdx.x;
    const int lane = t & 31, w = t >> 5;
    const int bbase = blockIdx.x * 4;
    const int jbase = blockIdx.y * (HID / K1SPLIT);

    float acc[32];
#pragma unroll
    for (int i = 0; i < 32; i++) acc[i] = 0.0f;

#pragma unroll
    for (int it = 0; it < 2; it++) {
        const int j = jbase + it * 1024 + t * 4;
        float4 h4[4];
#pragma unroll
        for (int bl = 0; bl < 4; bl++)
            h4[bl] = *(const float4*)(h + (bbase + bl) * HID + j);
        float4 r4[8];
#pragma unroll
        for (int r = 0; r < 8; r++)
            r4[r] = *(const float4*)(R + r * HID + j);

        float th[4][4];
#pragma unroll
        for (int bl = 0; bl < 4; bl++) {
            th[bl][0] = __tanhf(h4[bl].x);
            th[bl][1] = __tanhf(h4[bl].y);
            th[bl][2] = __tanhf(h4[bl].z);
            th[bl][3] = __tanhf(h4[bl].w);
        }
#pragma unroll
        for (int r = 0; r < 8; r++)
#pragma unroll
            for (int bl = 0; bl < 4; bl++) {
                float a = acc[bl * 8 + r];
                a = fmaf(th[bl][0], r4[r].x, a);
                a = fmaf(th[bl][1], r4[r].y, a);
                a = fmaf(th[bl][2], r4[r].z, a);
                a = fmaf(th[bl][3], r4[r].w, a);
                acc[bl * 8 + r] = a;
            }
    }

    // fold 32 values across 32 lanes: 31 SHFL; lane L -> total of acc[L]
#pragma unroll
    for (int m = 16; m >= 1; m >>= 1) {
        const bool up = (lane & m) != 0;
#pragma unroll
        for (int i = 0; i < m; i++) {
            float send = up ? acc[i] : acc[i + m];
            float got = __shfl_xor_sync(0xffffffffu, send, m);
            acc[i] = (up ? acc[i + m] : acc[i]) + got;
        }
    }

    __shared__ float red[8][32];
    red[w][lane] = acc[0];
    __syncthreads();
    if (t < 32) {
        float s = 0.0f;
#pragma unroll
        for (int w2 = 0; w2 < 8; w2++) s += red[w2][t];
        // acc index L: bl = L>>3, r = L&7  ->  (bbase+bl)*RANK + r = bbase*RANK + L
        g_u_part[blockIdx.y][bbase * RANK + t] = s;
    }
}

// ---------------------------------------------------------------------------
// K2: new_h = 0.9 h + 0.1 (input.W_in[j] + u.L[j]); u folded from partials
// into smem once per block. grid = (HID/64, BSPLIT) = 1024 blocks.
// Thread owns 4 j-columns with W_in/L in registers as f32x2 pairs.
// ---------------------------------------------------------------------------
__global__ void __launch_bounds__(256) k_update(const float* __restrict__ input,
                                                const float* __restrict__ hidden,
                                                const float* __restrict__ Win,
                                                const float* __restrict__ L,
                                                float* __restrict__ nh_out) {
    const int t = threadIdx.x;
    const int jg = t & 15;       // 16 groups of 4 j
    const int bs = t >> 4;       // 0..15
    const int j0 = blockIdx.x * 64 + jg * 4;
    const int b0 = blockIdx.y * (BATCH / BSPLIT);   // 64-row batch chunk

    __shared__ __align__(16) float u_s[BATCH / BSPLIT][RANK];

    // fold u partials for this batch chunk (deterministic fixed order)
#pragma unroll
    for (int v = t; v < (BATCH / BSPLIT) * RANK; v += 256) {
        const int bl = v >> 3, r = v & 7;
        float s = 0.0f;
#pragma unroll
        for (int p = 0; p < K1SPLIT; p++)
            s += g_u_part[p][(b0 + bl) * RANK + r];
        u_s[bl][r] = s * (1.0f / (float)HID);
    }

    ull wj[4][8];   // W_in[j][0..15] as 8 pairs
    ull lj[4][4];   // L[j][0..7]     as 4 pairs
#pragma unroll
    for (int jj = 0; jj < 4; jj++) {
        const ull* wr = (const ull*)(Win + (j0 + jj) * NIN);
#pragma unroll
        for (int i = 0; i < 8; i++) wj[jj][i] = wr[i];
        const ull* lr = (const ull*)(L + (j0 + jj) * RANK);
#pragma unroll
        for (int r = 0; r < 4; r++) lj[jj][r] = lr[r];
    }
    __syncthreads();

#pragma unroll
    for (int bi = bs; bi < BATCH / BSPLIT; bi += 16) {  // 4 iters
        const int b = b0 + bi;
        const ull* ip = (const ull*)(input + b * NIN);
        ull ipr[8];
#pragma unroll
        for (int i = 0; i < 8; i++) ipr[i] = ip[i];
        const ull* up = (const ull*)(&u_s[bi][0]);
        ull upr[4];
#pragma unroll
        for (int r = 0; r < 4; r++) upr[r] = up[r];

        float4 h4 = *(const float4*)(hidden + b * HID + j0);

        float res[4];
#pragma unroll
        for (int jj = 0; jj < 4; jj++) {
            ull acc = 0ULL;  // (0.0f, 0.0f)
#pragma unroll
            for (int i = 0; i < 8; i++) ffma2(acc, wj[jj][i], ipr[i]);
#pragma unroll
            for (int r = 0; r < 4; r++) ffma2(acc, lj[jj][r], upr[r]);
            float lo, hi;
            unpack2(lo, hi, acc);
            res[jj] = lo + hi;
        }

        float4 o;
        o.x = fmaf(0.1f, res[0], 0.9f * h4.x);
        o.y = fmaf(0.1f, res[1], 0.9f * h4.y);
        o.z = fmaf(0.1f, res[2], 0.9f * h4.z);
        o.w = fmaf(0.1f, res[3], 0.9f * h4.w);
        *(float4*)(nh_out + b * HID + j0) = o;
    }
}

// ---------------------------------------------------------------------------
// K3: out[b][o] = (1/H) sum_j tanh(new_h[b][j]) W_out[o][j]
// grid = BATCH/2 = 256 blocks, 2 batch rows each, full H sweep (8 iters),
// 8 accs folded in 9 SHFLs, direct final write (no combine kernel).
// ---------------------------------------------------------------------------
__global__ void __launch_bounds__(256) k_out(const float* __restrict__ nh,
                                             const float* __restrict__ Wout,
                                             float* __restrict__ out) {
    const int t = threadIdx.x;
    const int lane = t & 31, w = t >> 5;
    const int bbase = blockIdx.x * 2;

    float acc[8];
#pragma unroll
    for (int i = 0; i < 8; i++) acc[i] = 0.0f;

#pragma unroll
    for (int it = 0; it < 8; it++) {
        const int j = it * 1024 + t * 4;
        float4 x4[2];
#pragma unroll
        for (int bl = 0; bl < 2; bl++)
            x4[bl] = *(const float4*)(nh + (bbase + bl) * HID + j);
        float4 w4[4];
#pragma unroll
        for (int o = 0; o < 4; o++)
            w4[o] = *(const float4*)(Wout + o * HID + j);

        float th[2][4];
#pragma unroll
        for (int bl = 0; bl < 2; bl++) {
            th[bl][0] = __tanhf(x4[bl].x);
            th[bl][1] = __tanhf(x4[bl].y);
            th[bl][2] = __tanhf(x4[bl].z);
            th[bl][3] = __tanhf(x4[bl].w);
        }
#pragma unroll
        for (int o = 0; o < 4; o++)
#pragma unroll
            for (int bl = 0; bl < 2; bl++) {
                float a = acc[bl * 4 + o];
                a = fmaf(th[bl][0], w4[o].x, a);
                a = fmaf(th[bl][1], w4[o].y, a);
                a = fmaf(th[bl][2], w4[o].z, a);
                a = fmaf(th[bl][3], w4[o].w, a);
                acc[bl * 4 + o] = a;
            }
    }

    // fold 8 values over lane bits 0..2 (7 SHFL), then plain reduce bits 3,4
#pragma unroll
    for (int m = 4; m >= 1; m >>= 1) {
        const bool up = (lane & m) != 0;
#pragma unroll
        for (int i = 0; i < m; i++) {
            float send = up ? acc[i] : acc[i + m];
            float got = __shfl_xor_sync(0xffffffffu, send, m);
            acc[i] = (up ? acc[i + m] : acc[i]) + got;
        }
    }
    acc[0] += __shfl_xor_sync(0xffffffffu, acc[0], 8);
    acc[0] += __shfl_xor_sync(0xffffffffu, acc[0], 16);
    // lane L holds total of acc[L&7]

    __shared__ float red[8][8];
    if (lane < 8) red[w][lane] = acc[0];
    __syncthreads();
    if (t < 8) {
        float s = 0.0f;
#pragma unroll
        for (int w2 = 0; w2 < 8; w2++) s += red[w2][t];
        const int bl = t >> 2, o = t & 3;
        out[(bbase + bl) * NOUT + o] = s * (1.0f / (float)HID);
    }
}

extern "C" void kernel_launch(void* const* d_in, const int* in_sizes, int n_in,
                              void* d_out, int out_size) {
    const float* input  = (const float*)d_in[0];  // [512,16]
    const float* hidden = (const float*)d_in[1];  // [512,8192]
    const float* Win    = (const float*)d_in[2];  // [8192,16]
    const float* L      = (const float*)d_in[3];  // [8192,8]
    const float* R      = (const float*)d_in[4];  // [8,8192]
    const float* Wout   = (const float*)d_in[5];  // [4,8192]

    float* out = (float*)d_out;                   // [512,4] then [512,8192]
    float* nh  = out + BATCH * NOUT;

    k_rank<<<dim3(BATCH / 4, K1SPLIT), 256>>>(hidden, R);
    k_update<<<dim3(HID / 64, BSPLIT), 256>>>(input, hidden, Win, L, nh);
    k_out<<<BATCH / 2, 256>>>(nh, Wout, out);
}

// round 5
// speedup vs baseline: 3.5012x; 2.3353x over previous
#include <cuda_runtime.h>

#define HID 8192
#define BATCH 512
#define NIN 16
#define RANK 8
#define NOUT 4
#define GRID 256
#define TPB 256

// u partials: two H-halves, folded in phase 2 (fixed order => deterministic)
__device__ float g_u_part[2][BATCH * RANK];
__device__ unsigned int g_bar;   // monotone ticket counter, never reset (replay-safe)

typedef unsigned long long ull;

__device__ __forceinline__ void ffma2(ull& d, ull a, ull b) {
    asm("fma.rn.f32x2 %0, %1, %2, %0;" : "+l"(d) : "l"(a), "l"(b));
}
__device__ __forceinline__ void unpack2(float& lo, float& hi, ull v) {
    asm("mov.b64 {%0, %1}, %2;" : "=f"(lo), "=f"(hi) : "l"(v));
}

__device__ __forceinline__ void grid_barrier() {
    __syncthreads();
    if (threadIdx.x == 0) {
        __threadfence();
        unsigned int old = atomicAdd(&g_bar, 1u);
        unsigned int target = (old / GRID + 1u) * GRID;   // end of this barrier instance
        while ((int)(*(volatile unsigned int*)&g_bar - target) < 0)
            __nanosleep(32);
        __threadfence();
    }
    __syncthreads();
}

__global__ void __launch_bounds__(TPB, 2) k_fused(const float* __restrict__ input,
                                                  const float* __restrict__ hidden,
                                                  const float* __restrict__ Win,
                                                  const float* __restrict__ L,
                                                  const float* __restrict__ R,
                                                  const float* __restrict__ Wout,
                                                  float* __restrict__ nh,
                                                  float* __restrict__ out) {
    const int t = threadIdx.x;
    const int lane = t & 31, w = t >> 5;

    __shared__ float red[8][32];
    __shared__ __align__(16) float u_s[64][RANK];    // phase 2
    __shared__ __align__(16) float in_s[64][NIN];    // phase 2

    // ===================== Phase 1: u partials ============================
    {
        const int bg = blockIdx.x >> 1;          // 0..127 -> 4 batch rows
        const int half = blockIdx.x & 1;         // H-half
        const int bbase = bg * 4;

        float acc[32];
#pragma unroll
        for (int i = 0; i < 32; i++) acc[i] = 0.0f;

#pragma unroll
        for (int it = 0; it < 4; it++) {
            const int j = half * 4096 + it * 1024 + t * 4;
            float4 h4[4];
#pragma unroll
            for (int bl = 0; bl < 4; bl++)
                h4[bl] = *(const float4*)(hidden + (bbase + bl) * HID + j);
            float th[4][4];
#pragma unroll
            for (int bl = 0; bl < 4; bl++) {
                th[bl][0] = __tanhf(h4[bl].x);
                th[bl][1] = __tanhf(h4[bl].y);
                th[bl][2] = __tanhf(h4[bl].z);
                th[bl][3] = __tanhf(h4[bl].w);
            }
#pragma unroll
            for (int r = 0; r < 8; r++) {
                float4 rv = *(const float4*)(R + r * HID + j);
#pragma unroll
                for (int bl = 0; bl < 4; bl++) {
                    float a = acc[bl * 8 + r];
                    a = fmaf(th[bl][0], rv.x, a);
                    a = fmaf(th[bl][1], rv.y, a);
                    a = fmaf(th[bl][2], rv.z, a);
                    a = fmaf(th[bl][3], rv.w, a);
                    acc[bl * 8 + r] = a;
                }
            }
        }

        // fold 32 values across lanes: 31 SHFL, lane L ends with total of acc[L]
#pragma unroll
        for (int m = 16; m >= 1; m >>= 1) {
            const bool up = (lane & m) != 0;
#pragma unroll
            for (int i = 0; i < m; i++) {
                float send = up ? acc[i] : acc[i + m];
                float got = __shfl_xor_sync(0xffffffffu, send, m);
                acc[i] = (up ? acc[i + m] : acc[i]) + got;
            }
        }
        red[w][lane] = acc[0];
        __syncthreads();
        if (t < 32) {
            float s = 0.0f;
#pragma unroll
            for (int w2 = 0; w2 < 8; w2++) s += red[w2][t];
            g_u_part[half][bbase * RANK + t] = s;   // L -> (bbase + L>>3)*8 + (L&7)
        }
    }

    grid_barrier();

    // ===================== Phase 2: new_h =================================
    {
        const int jt = blockIdx.x & 31;          // 32 j-tiles of 256
        const int bc = blockIdx.x >> 5;          // 8 batch chunks of 64
        const int b0 = bc * 64;
        const int jg = t & 127;                  // 128 groups of 2 j
        const int bs = t >> 7;                   // 0..1
        const int j0 = jt * 256 + jg * 2;

        // fold u partials + stage input rows (deterministic fixed order)
        for (int v = t; v < 64 * RANK; v += TPB) {
            const int idx = b0 * RANK + v;
            u_s[v >> 3][v & 7] =
                (g_u_part[0][idx] + g_u_part[1][idx]) * (1.0f / (float)HID);
        }
        for (int v = t; v < 64 * NIN; v += TPB)
            in_s[v >> 4][v & 15] = input[b0 * NIN + v];

        ull wj[2][8];
        ull lj[2][4];
#pragma unroll
        for (int jj = 0; jj < 2; jj++) {
            const ull* wr = (const ull*)(Win + (j0 + jj) * NIN);
#pragma unroll
            for (int i = 0; i < 8; i++) wj[jj][i] = wr[i];
            const ull* lr = (const ull*)(L + (j0 + jj) * RANK);
#pragma unroll
            for (int r = 0; r < 4; r++) lj[jj][r] = lr[r];
        }
        __syncthreads();

#pragma unroll 4
        for (int bi = bs; bi < 64; bi += 2) {
            const int b = b0 + bi;
            const ull* ip = (const ull*)&in_s[bi][0];
            const ull* up = (const ull*)&u_s[bi][0];

            float2 h2 = *(const float2*)(hidden + b * HID + j0);

            float res[2];
#pragma unroll
            for (int jj = 0; jj < 2; jj++) {
                ull acc = 0ULL;
#pragma unroll
                for (int i = 0; i < 8; i++) ffma2(acc, wj[jj][i], ip[i]);
#pragma unroll
                for (int r = 0; r < 4; r++) ffma2(acc, lj[jj][r], up[r]);
                float lo, hi;
                unpack2(lo, hi, acc);
                res[jj] = lo + hi;
            }

            float2 o;
            o.x = fmaf(0.1f, res[0], 0.9f * h2.x);
            o.y = fmaf(0.1f, res[1], 0.9f * h2.y);
            *(float2*)(nh + b * HID + j0) = o;
        }
    }

    grid_barrier();

    // ===================== Phase 3: output ================================
    {
        const int bbase = blockIdx.x * 2;

        float acc[8];
#pragma unroll
        for (int i = 0; i < 8; i++) acc[i] = 0.0f;

#pragma unroll
        for (int it = 0; it < 8; it++) {
            const int j = it * 1024 + t * 4;
            float4 x4[2];
#pragma unroll
            for (int bl = 0; bl < 2; bl++)
                x4[bl] = *(const float4*)(nh + (bbase + bl) * HID + j);
            float th[2][4];
#pragma unroll
            for (int bl = 0; bl < 2; bl++) {
                th[bl][0] = __tanhf(x4[bl].x);
                th[bl][1] = __tanhf(x4[bl].y);
                th[bl][2] = __tanhf(x4[bl].z);
                th[bl][3] = __tanhf(x4[bl].w);
            }
#pragma unroll
            for (int o = 0; o < 4; o++) {
                float4 w4 = *(const float4*)(Wout + o * HID + j);
#pragma unroll
                for (int bl = 0; bl < 2; bl++) {
                    float a = acc[bl * 4 + o];
                    a = fmaf(th[bl][0], w4.x, a);
                    a = fmaf(th[bl][1], w4.y, a);
                    a = fmaf(th[bl][2], w4.z, a);
                    a = fmaf(th[bl][3], w4.w, a);
                    acc[bl * 4 + o] = a;
                }
            }
        }

        // fold 8 values over lane bits 0..2, then reduce bits 3,4
#pragma unroll
        for (int m = 4; m >= 1; m >>= 1) {
            const bool up = (lane & m) != 0;
#pragma unroll
            for (int i = 0; i < m; i++) {
                float send = up ? acc[i] : acc[i + m];
                float got = __shfl_xor_sync(0xffffffffu, send, m);
                acc[i] = (up ? acc[i + m] : acc[i]) + got;
            }
        }
        acc[0] += __shfl_xor_sync(0xffffffffu, acc[0], 8);
        acc[0] += __shfl_xor_sync(0xffffffffu, acc[0], 16);

        __syncthreads();   // red[] reuse
        if (lane < 8) red[w][lane] = acc[0];
        __syncthreads();
        if (t < 8) {
            float s = 0.0f;
#pragma unroll
            for (int w2 = 0; w2 < 8; w2++) s += red[w2][t];
            out[(bbase + (t >> 2)) * NOUT + (t & 3)] = s * (1.0f / (float)HID);
        }
    }
}

extern "C" void kernel_launch(void* const* d_in, const int* in_sizes, int n_in,
                              void* d_out, int out_size) {
    const float* input  = (const float*)d_in[0];  // [512,16]
    const float* hidden = (const float*)d_in[1];  // [512,8192]
    const float* Win    = (const float*)d_in[2];  // [8192,16]
    const float* L      = (const float*)d_in[3];  // [8192,8]
    const float* R      = (const float*)d_in[4];  // [8,8192]
    const float* Wout   = (const float*)d_in[5];  // [4,8192]

    float* out = (float*)d_out;                   // [512,4] then [512,8192]
    float* nh  = out + BATCH * NOUT;

    k_fused<<<GRID, TPB>>>(input, hidden, Win, L, R, Wout, nh, out);
}